// round 10
// baseline (speedup 1.0000x reference)
#include <cuda_runtime.h>
#include <math.h>

#define BN 8192
#define FN 8192
#define DN 1024
#define H1N 256
#define H2N 64
#define NZC 102
#define CAP 128
#define MARGIN 0.22f

// ---------------- scratch (device globals; no allocations allowed) ----------
__device__ float g_a1[BN * H1N];
__device__ float g_a2[BN * H2N];
__device__ double g_ps[64 * 256], g_pq[64 * 256];     // layer-1 stats partials
__device__ double g_ps2[512 * 64], g_pq2[512 * 64];   // layer-2 stats partials
__device__ float g_sc1v[H1N], g_sh1v[H1N];
__device__ float g_sc2v[H2N], g_sh2v[H2N];
__device__ int   g_ind[BN];

// ---------------- threefry-2x32, key = (0, 42) ------------------------------
__device__ __forceinline__ unsigned int jax_bits(unsigned int j) {
    const unsigned int k0 = 0u, k1 = 42u;
    const unsigned int k2 = 0x1BD11BDAu ^ k0 ^ k1;
    unsigned int x0 = 0u + k0, x1 = j + k1;
#define TF_R(r) { x0 += x1; x1 = (x1 << (r)) | (x1 >> (32 - (r))); x1 ^= x0; }
    TF_R(13) TF_R(15) TF_R(26) TF_R(6)
    x0 += k1; x1 += k2 + 1u;
    TF_R(17) TF_R(29) TF_R(16) TF_R(24)
    x0 += k2; x1 += k0 + 2u;
    TF_R(13) TF_R(15) TF_R(26) TF_R(6)
    x0 += k0; x1 += k1 + 3u;
    TF_R(17) TF_R(29) TF_R(16) TF_R(24)
    x0 += k1; x1 += k2 + 4u;
    TF_R(13) TF_R(15) TF_R(26) TF_R(6)
    x0 += k2; x1 += k0 + 5u;
#undef TF_R
    return x0 ^ x1;   // partitionable 32-bit: bits1 ^ bits2
}

__device__ __forceinline__ float gumbel_ref(unsigned int b) {
    float u = __uint_as_float((b >> 9) | 0x3F800000u) - 1.0f;   // [0,1)
    float U = __fmul_rn(0.001f, u);
    float t = __fadd_rn(U, 0.001f);
    float l1 = logf(t);
    float a  = __fadd_rn(-l1, 0.001f);
    return -logf(a);                      // [-1.93285, -1.82711]
}

__device__ __forceinline__ unsigned int encf(float f) {
    unsigned int u = __float_as_uint(f);
    return (u & 0x80000000u) ? ~u : (u | 0x80000000u);
}
__device__ __forceinline__ float decf(unsigned int e) {
    unsigned int u = (e & 0x80000000u) ? (e ^ 0x80000000u) : ~e;
    return __uint_as_float(u);
}

// ---------------- bf16 helpers ----------------------------------------------
__device__ __forceinline__ unsigned pkbf(float lo, float hi) {
    unsigned r;
    asm("cvt.rn.bf16x2.f32 %0, %1, %2;" : "=r"(r) : "f"(hi), "f"(lo));
    return r;   // low half = lo, high half = hi
}
__device__ __forceinline__ void mma_bf16(float* c, const unsigned* a,
                                         unsigned b0, unsigned b1) {
    asm("mma.sync.aligned.m16n8k16.row.col.f32.bf16.bf16.f32 "
        "{%0,%1,%2,%3},{%4,%5,%6,%7},{%8,%9},{%0,%1,%2,%3};"
        : "+f"(c[0]), "+f"(c[1]), "+f"(c[2]), "+f"(c[3])
        : "r"(a[0]), "r"(a[1]), "r"(a[2]), "r"(a[3]), "r"(b0), "r"(b1));
}

// ---------------- K1: a1 = concat(x,y) @ W1 + b1 ----------------------------
__global__ __launch_bounds__(256) void k1_gemm1(const float* __restrict__ x,
                                                const float* __restrict__ y,
                                                const float* __restrict__ W1,
                                                const float* __restrict__ b1) {
    __shared__ float zs[8][NZC];
    const int rb = blockIdx.x * 8;
    const int tid = threadIdx.x;
    for (int i = tid; i < 8 * NZC; i += 256) {
        int r = i / NZC, c = i % NZC;
        zs[r][c] = (c < 100) ? x[(rb + r) * 100 + c] : y[(rb + r) * 2 + (c - 100)];
    }
    __syncthreads();
    const int col = tid;
    float acc[8];
#pragma unroll
    for (int r = 0; r < 8; r++) acc[r] = 0.0f;
    for (int k = 0; k < NZC; k++) {
        float w = W1[k * 256 + col];
#pragma unroll
        for (int r = 0; r < 8; r++) acc[r] = fmaf(zs[r][k], w, acc[r]);
    }
    const float bb = b1[col];
#pragma unroll
    for (int r = 0; r < 8; r++) g_a1[(rb + r) * 256 + col] = acc[r] + bb;
}

// ---------------- kstats1: layer-1 per-column double partials ---------------
__global__ __launch_bounds__(256) void kstats1() {
    const int tid = threadIdx.x, b = blockIdx.x;   // 64 blocks
    double s0 = 0.0, s1 = 0.0, q0 = 0.0, q1 = 0.0;
    const int rb = b * 128;
    for (int s = 0; s < 128; s += 2) {
        float v0 = g_a1[(rb + s) * 256 + tid];
        float v1 = g_a1[(rb + s + 1) * 256 + tid];
        s0 += (double)v0; q0 = fma((double)v0, (double)v0, q0);
        s1 += (double)v1; q1 = fma((double)v1, (double)v1, q1);
    }
    g_ps[b * 256 + tid] = s0 + s1;
    g_pq[b * 256 + tid] = q0 + q1;
}

// ---------------- kstats2a: layer-1 scale/shift (tiny) ----------------------
__global__ void kstats2a(const float* __restrict__ g1v,
                         const float* __restrict__ be1) {
    const int c = threadIdx.x;   // 256 threads
    double sa = 0.0, sb = 0.0, qa = 0.0, qb = 0.0;
    for (int b = 0; b < 64; b += 2) {
        sa += g_ps[b * 256 + c];       qa += g_pq[b * 256 + c];
        sb += g_ps[(b + 1) * 256 + c]; qb += g_pq[(b + 1) * 256 + c];
    }
    double s = sa + sb, q = qa + qb;
    double mean = s / (double)BN;
    double var  = q / (double)BN - mean * mean;
    float rstd = (float)(1.0 / sqrt(var + 1e-5));
    float scale = g1v[c] * rstd;
    g_sc1v[c] = scale;
    g_sh1v[c] = be1[c] - (float)mean * scale;
}

// ---------------- K3: a2 = relu(BN(a1)) @ W2 + b2, + L2 partials ------------
__global__ __launch_bounds__(256) void k3_gemm2(const float* __restrict__ W2,
                                                const float* __restrict__ b2) {
    __shared__ float h1s[16][256];
    __shared__ double sst[256], qst[256];
    const int rb = blockIdx.x * 16;
    const int tid = threadIdx.x;
    const float sc = g_sc1v[tid], sh = g_sh1v[tid];
#pragma unroll 4
    for (int r = 0; r < 16; r++) {
        float v = g_a1[(rb + r) * 256 + tid] * sc + sh;
        h1s[r][tid] = fmaxf(v, 0.0f);
    }
    __syncthreads();
    const int c  = tid & 63;
    const int rq = tid >> 6;
    float acc[4] = {0.f, 0.f, 0.f, 0.f};
    for (int k = 0; k < 256; k += 4) {
        float w0 = W2[(k + 0) * 64 + c];
        float w1 = W2[(k + 1) * 64 + c];
        float w2v = W2[(k + 2) * 64 + c];
        float w3v = W2[(k + 3) * 64 + c];
#pragma unroll
        for (int i = 0; i < 4; i++) {
            const float4 h = *reinterpret_cast<const float4*>(&h1s[rq * 4 + i][k]);
            acc[i] = fmaf(h.x, w0, acc[i]);
            acc[i] = fmaf(h.y, w1, acc[i]);
            acc[i] = fmaf(h.z, w2v, acc[i]);
            acc[i] = fmaf(h.w, w3v, acc[i]);
        }
    }
    const float bc = b2[c];
    float o[4];
#pragma unroll
    for (int i = 0; i < 4; i++) {
        o[i] = acc[i] + bc;
        g_a2[(rb + rq * 4 + i) * 64 + c] = o[i];
    }
    double s = (((double)o[0] + (double)o[1]) + (double)o[2]) + (double)o[3];
    double q = 0.0;
#pragma unroll
    for (int i = 0; i < 4; i++) q = fma((double)o[i], (double)o[i], q);
    sst[rq * 64 + c] = s; qst[rq * 64 + c] = q;
    __syncthreads();
    if (rq == 0) {
        double S = ((sst[c] + sst[64 + c]) + sst[128 + c]) + sst[192 + c];
        double Q = ((qst[c] + qst[64 + c]) + qst[128 + c]) + qst[192 + c];
        g_ps2[blockIdx.x * 64 + c] = S;
        g_pq2[blockIdx.x * 64 + c] = Q;
    }
}

// ---------------- kstats2b: layer-2 scale/shift (tiny) ----------------------
__global__ void kstats2b(const float* __restrict__ g2v,
                         const float* __restrict__ be2) {
    const int c = threadIdx.x;   // 64 threads
    double sa = 0.0, sb = 0.0, qa = 0.0, qb = 0.0;
    for (int b = 0; b < 512; b += 2) {
        sa += g_ps2[b * 64 + c];       qa += g_pq2[b * 64 + c];
        sb += g_ps2[(b + 1) * 64 + c]; qb += g_pq2[(b + 1) * 64 + c];
    }
    double S = sa + sb, Q = qa + qb;
    double mean = S / (double)BN;
    double var  = Q / (double)BN - mean * mean;
    float rstd = (float)(1.0 / sqrt(var + 1e-5));
    float scale = g2v[c] * rstd;
    g_sc2v[c] = scale;
    g_sh2v[c] = be2[c] - (float)mean * scale;
}

// ---------------- K5: bf16 MMA logits + bounded-gumbel candidate argmax -----
// 256 blocks x 32 rows, 44KB static smem (~3 blocks/SM). Warp = (m-subtile,
// n16-quarter): 8 MMAs per 64-feature tile, 128 tiles, one barrier per tile
// (double-buffered smem W, pre-packed bf16x2, stride-72 conflict-free).
// Register thresholds refreshed from shared row max each tile (monotone =>
// safe superset). Exact fp32+threefry refine decides winners.
__global__ __launch_bounds__(256) void k5_mma(const float* __restrict__ W3,
                                              const float* __restrict__ b3) {
    __shared__ float    h2f[32 * 68];
    __shared__ unsigned wsb[2 * 2304];      // 2 x [32 kp][72]
    __shared__ int      cand[32 * CAP];
    __shared__ unsigned rmx[32];
    __shared__ int      scnt[32];

    const int tid = threadIdx.x, lane = tid & 31, wid = tid >> 5;
    const int g = lane >> 2, c4 = lane & 3;
    const int rb = blockIdx.x * 32;

    for (int i = tid; i < 32 * 64; i += 256) {
        int r = i >> 6, k = i & 63;
        float v = g_a2[(rb + r) * 64 + k] * g_sc2v[k] + g_sh2v[k];
        h2f[r * 68 + k] = fmaxf(v, 0.0f);
    }
    if (tid < 32) { rmx[tid] = encf(-1e30f); scnt[tid] = 0; }
    __syncthreads();

    const int m  = wid & 1;    // m16 subtile
    const int nq = wid >> 1;   // n16 quarter of the 64-wide tile

    // A fragments (bf16, verified layout): [kstep][4]
    unsigned au[4][4];
#pragma unroll
    for (int s = 0; s < 4; s++) {
        int r0 = m * 16 + g, r1 = r0 + 8;
        int kA = 16 * s + 2 * c4, kB = kA + 8;
        au[s][0] = pkbf(h2f[r0 * 68 + kA], h2f[r0 * 68 + kA + 1]);
        au[s][1] = pkbf(h2f[r1 * 68 + kA], h2f[r1 * 68 + kA + 1]);
        au[s][2] = pkbf(h2f[r0 * 68 + kB], h2f[r0 * 68 + kB + 1]);
        au[s][3] = pkbf(h2f[r1 * 68 + kB], h2f[r1 * 68 + kB + 1]);
    }

    // stage W tile 0 (kp = k-pair 0..31, fq = feature quad 0..7)
    const int kp = tid >> 3, fq = tid & 7;
    {
        const float* p = W3 + (size_t)(2 * kp) * FN + fq * 4;
        float4 A0 = *reinterpret_cast<const float4*>(p);
        float4 B0 = *reinterpret_cast<const float4*>(p + FN);
        float4 A1 = *reinterpret_cast<const float4*>(p + 32);
        float4 B1 = *reinterpret_cast<const float4*>(p + FN + 32);
        *reinterpret_cast<uint4*>(&wsb[kp * 72 + fq * 4]) =
            make_uint4(pkbf(A0.x, B0.x), pkbf(A0.y, B0.y), pkbf(A0.z, B0.z), pkbf(A0.w, B0.w));
        *reinterpret_cast<uint4*>(&wsb[kp * 72 + 32 + fq * 4]) =
            make_uint4(pkbf(A1.x, B1.x), pkbf(A1.y, B1.y), pkbf(A1.z, B1.z), pkbf(A1.w, B1.w));
    }
    __syncthreads();

    const int rlo = m * 16 + g, rhi = rlo + 8;
    float rml = -1e30f, rmh = -1e30f;
    float thrlo = -1e30f, thrhi = -1e30f;

    for (int t = 0; t < 128; t++) {
        const int f0 = t * 64;
        unsigned* wcur = wsb + (t & 1) * 2304;
        float4 A0, B0, A1, B1;
        if (t < 127) {
            const float* p = W3 + (size_t)(2 * kp) * FN + f0 + 64 + fq * 4;
            A0 = *reinterpret_cast<const float4*>(p);
            B0 = *reinterpret_cast<const float4*>(p + FN);
            A1 = *reinterpret_cast<const float4*>(p + 32);
            B1 = *reinterpret_cast<const float4*>(p + FN + 32);
        }
        float acc[2][4];
#pragma unroll
        for (int h = 0; h < 2; h++) { acc[h][0] = acc[h][1] = acc[h][2] = acc[h][3] = 0.f; }
#pragma unroll
        for (int h = 0; h < 2; h++) {
            const int base = nq * 16 + h * 8 + g;
#pragma unroll
            for (int s = 0; s < 4; s++) {
                unsigned bb0 = wcur[(8 * s + c4) * 72 + base];
                unsigned bb1 = wcur[(8 * s + c4 + 4) * 72 + base];
                mma_bf16(acc[h], au[s], bb0, bb1);
            }
        }
        // refresh thresholds from shared row max (monotone: safe)
        thrlo = fmaxf(thrlo, decf(*(volatile unsigned*)&rmx[rlo]) - MARGIN);
        thrhi = fmaxf(thrhi, decf(*(volatile unsigned*)&rmx[rhi]) - MARGIN);
#pragma unroll
        for (int h = 0; h < 2; h++) {
            const int fc = f0 + nq * 16 + h * 8 + 2 * c4;
            const float2 bias = *reinterpret_cast<const float2*>(b3 + fc);
            float v0 = acc[h][0] + bias.x, v1 = acc[h][1] + bias.y;
            float v2 = acc[h][2] + bias.x, v3 = acc[h][3] + bias.y;
            float m01 = fmaxf(v0, v1), m23 = fmaxf(v2, v3);
            if (m01 > rml) {
                rml = m01; thrlo = fmaxf(thrlo, m01 - MARGIN);
                atomicMax(&rmx[rlo], encf(m01));
            }
            if (m23 > rmh) {
                rmh = m23; thrhi = fmaxf(thrhi, m23 - MARGIN);
                atomicMax(&rmx[rhi], encf(m23));
            }
            if (v0 > thrlo) { int p = atomicAdd(&scnt[rlo], 1); if (p < CAP) cand[rlo * CAP + p] = fc; }
            if (v1 > thrlo) { int p = atomicAdd(&scnt[rlo], 1); if (p < CAP) cand[rlo * CAP + p] = fc + 1; }
            if (v2 > thrhi) { int p = atomicAdd(&scnt[rhi], 1); if (p < CAP) cand[rhi * CAP + p] = fc; }
            if (v3 > thrhi) { int p = atomicAdd(&scnt[rhi], 1); if (p < CAP) cand[rhi * CAP + p] = fc + 1; }
        }
        if (t < 127) {
            unsigned* wnxt = wsb + ((t + 1) & 1) * 2304;
            *reinterpret_cast<uint4*>(&wnxt[kp * 72 + fq * 4]) =
                make_uint4(pkbf(A0.x, B0.x), pkbf(A0.y, B0.y), pkbf(A0.z, B0.z), pkbf(A0.w, B0.w));
            *reinterpret_cast<uint4*>(&wnxt[kp * 72 + 32 + fq * 4]) =
                make_uint4(pkbf(A1.x, B1.x), pkbf(A1.y, B1.y), pkbf(A1.z, B1.z), pkbf(A1.w, B1.w));
        }
        __syncthreads();
    }

    // ---- exact refine: warp w owns rows w, w+8, w+16, w+24 ----
    for (int rr = wid; rr < 32; rr += 8) {
        const int row = rb + rr;
        const int c = scnt[rr];
        float bestv = -1e30f; int bestf = 0x7FFFFFFF;
        if (c <= CAP) {
            for (int i = lane; i < c; i += 32) {
                int f = cand[rr * CAP + i];
                float dot = 0.f;
#pragma unroll
                for (int k = 0; k < 64; k++)
                    dot = fmaf(h2f[rr * 68 + k], W3[k * FN + f], dot);
                float logit = __fadd_rn(dot, b3[f]);
                float gg = gumbel_ref(jax_bits((unsigned)row * 8192u + (unsigned)f));
                float v = __fdiv_rn(__fadd_rn(logit, gg), 0.1f);
                if (v > bestv || (v == bestv && f < bestf)) { bestv = v; bestf = f; }
            }
        } else {   // overflow fallback: exact full-row scan with threshold filter
            float th = decf(rmx[rr]) - MARGIN;
            for (int f = lane; f < FN; f += 32) {
                float dot = 0.f;
#pragma unroll
                for (int k = 0; k < 64; k++)
                    dot = fmaf(h2f[rr * 68 + k], W3[k * FN + f], dot);
                float logit = __fadd_rn(dot, b3[f]);
                if (logit > th) {
                    float gg = gumbel_ref(jax_bits((unsigned)row * 8192u + (unsigned)f));
                    float v = __fdiv_rn(__fadd_rn(logit, gg), 0.1f);
                    if (v > bestv || (v == bestv && f < bestf)) { bestv = v; bestf = f; }
                }
            }
        }
#pragma unroll
        for (int off = 16; off > 0; off >>= 1) {
            float ov = __shfl_xor_sync(0xFFFFFFFFu, bestv, off);
            int   of = __shfl_xor_sync(0xFFFFFFFFu, bestf, off);
            if (ov > bestv || (ov == bestv && of < bestf)) { bestv = ov; bestf = of; }
        }
        if (lane == 0) g_ind[row] = bestf;
    }
}

// ---------------- K7: out[row] = codebook[ind[row]] -------------------------
__global__ void k7_gather(const float* __restrict__ codebook, float* __restrict__ out) {
    const int row = blockIdx.x;
    const int ind = g_ind[row];
    const float4* src = reinterpret_cast<const float4*>(codebook + (size_t)ind * DN);
    float4* dst = reinterpret_cast<float4*>(out + (size_t)row * DN);
    dst[threadIdx.x] = src[threadIdx.x];
}

// ---------------- launch ----------------------------------------------------
extern "C" void kernel_launch(void* const* d_in, const int* in_sizes, int n_in,
                              void* d_out, int out_size) {
    const float* x   = (const float*)d_in[0];
    const float* y   = (const float*)d_in[1];
    const float* W1  = (const float*)d_in[2];
    const float* b1  = (const float*)d_in[3];
    const float* g1  = (const float*)d_in[4];
    const float* be1 = (const float*)d_in[5];
    const float* W2  = (const float*)d_in[6];
    const float* b2  = (const float*)d_in[7];
    const float* g2  = (const float*)d_in[8];
    const float* be2 = (const float*)d_in[9];
    const float* W3  = (const float*)d_in[10];
    const float* b3  = (const float*)d_in[11];
    const float* cb  = (const float*)d_in[12];
    float* out = (float*)d_out;

    k1_gemm1<<<BN / 8, 256>>>(x, y, W1, b1);
    kstats1<<<64, 256>>>();
    kstats2a<<<1, H1N>>>(g1, be1);
    k3_gemm2<<<BN / 16, 256>>>(W2, b2);
    kstats2b<<<1, H2N>>>(g2, be2);
    k5_mma<<<BN / 32, 256>>>(W3, b3);
    k7_gather<<<BN, 256>>>(cb, out);
}

// round 13
// speedup vs baseline: 2.9647x; 2.9647x over previous
#include <cuda_runtime.h>
#include <math.h>

#define BN 8192
#define FN 8192
#define DN 1024
#define H1N 256
#define H2N 64
#define NZC 102
#define CAP 64
#define MARGIN 0.16f

// ---------------- scratch (device globals; no allocations allowed) ----------
__device__ float g_a1[BN * H1N];
__device__ float g_a2[BN * H2N];
__device__ double g_ps[64 * 256], g_pq[64 * 256];     // layer-1 stats partials
__device__ double g_ps2[512 * 64], g_pq2[512 * 64];   // layer-2 stats partials
__device__ float g_sc1v[H1N], g_sh1v[H1N];
__device__ float g_sc2v[H2N], g_sh2v[H2N];
__device__ unsigned g_w3bf[32 * FN];                  // bf16x2 {k=2kp, k=2kp+1} per feature
__device__ int   g_ind[BN];

// ---------------- threefry-2x32, key = (0, 42) ------------------------------
__device__ __forceinline__ unsigned int jax_bits(unsigned int j) {
    const unsigned int k0 = 0u, k1 = 42u;
    const unsigned int k2 = 0x1BD11BDAu ^ k0 ^ k1;
    unsigned int x0 = 0u + k0, x1 = j + k1;
#define TF_R(r) { x0 += x1; x1 = (x1 << (r)) | (x1 >> (32 - (r))); x1 ^= x0; }
    TF_R(13) TF_R(15) TF_R(26) TF_R(6)
    x0 += k1; x1 += k2 + 1u;
    TF_R(17) TF_R(29) TF_R(16) TF_R(24)
    x0 += k2; x1 += k0 + 2u;
    TF_R(13) TF_R(15) TF_R(26) TF_R(6)
    x0 += k0; x1 += k1 + 3u;
    TF_R(17) TF_R(29) TF_R(16) TF_R(24)
    x0 += k1; x1 += k2 + 4u;
    TF_R(13) TF_R(15) TF_R(26) TF_R(6)
    x0 += k2; x1 += k0 + 5u;
#undef TF_R
    return x0 ^ x1;   // partitionable 32-bit: bits1 ^ bits2
}

__device__ __forceinline__ float gumbel_ref(unsigned int b) {
    float u = __uint_as_float((b >> 9) | 0x3F800000u) - 1.0f;   // [0,1)
    float U = __fmul_rn(0.001f, u);
    float t = __fadd_rn(U, 0.001f);
    float l1 = logf(t);
    float a  = __fadd_rn(-l1, 0.001f);
    return -logf(a);                      // [-1.93285, -1.82711]
}

__device__ __forceinline__ unsigned int encf(float f) {
    unsigned int u = __float_as_uint(f);
    return (u & 0x80000000u) ? ~u : (u | 0x80000000u);
}
__device__ __forceinline__ float decf(unsigned int e) {
    unsigned int u = (e & 0x80000000u) ? (e ^ 0x80000000u) : ~e;
    return __uint_as_float(u);
}

// ---------------- bf16 helpers ----------------------------------------------
__device__ __forceinline__ unsigned pkbf(float lo, float hi) {
    unsigned r;
    asm("cvt.rn.bf16x2.f32 %0, %1, %2;" : "=r"(r) : "f"(hi), "f"(lo));
    return r;   // low half = lo, high half = hi
}
__device__ __forceinline__ void mma_bf16(float* c, const unsigned* a,
                                         unsigned b0, unsigned b1) {
    asm("mma.sync.aligned.m16n8k16.row.col.f32.bf16.bf16.f32 "
        "{%0,%1,%2,%3},{%4,%5,%6,%7},{%8,%9},{%0,%1,%2,%3};"
        : "+f"(c[0]), "+f"(c[1]), "+f"(c[2]), "+f"(c[3])
        : "r"(a[0]), "r"(a[1]), "r"(a[2]), "r"(a[3]), "r"(b0), "r"(b1));
}

// ---------------- k0pack: W3 -> bf16x2 k-pair layout (coalesced) ------------
__global__ __launch_bounds__(256) void k0pack(const float* __restrict__ W3) {
    const int t = blockIdx.x * 256 + threadIdx.x;   // 256K threads
    const int kp = t >> 13, f = t & 8191;
    g_w3bf[t] = pkbf(W3[(2 * kp) * FN + f], W3[(2 * kp + 1) * FN + f]);
}

// ---------------- K1: a1 = concat(x,y) @ W1 + b1 ----------------------------
__global__ __launch_bounds__(256) void k1_gemm1(const float* __restrict__ x,
                                                const float* __restrict__ y,
                                                const float* __restrict__ W1,
                                                const float* __restrict__ b1) {
    __shared__ float zs[8][NZC];
    const int rb = blockIdx.x * 8;
    const int tid = threadIdx.x;
    for (int i = tid; i < 8 * NZC; i += 256) {
        int r = i / NZC, c = i % NZC;
        zs[r][c] = (c < 100) ? x[(rb + r) * 100 + c] : y[(rb + r) * 2 + (c - 100)];
    }
    __syncthreads();
    const int col = tid;
    float acc[8];
#pragma unroll
    for (int r = 0; r < 8; r++) acc[r] = 0.0f;
    for (int k = 0; k < NZC; k++) {
        float w = W1[k * 256 + col];
#pragma unroll
        for (int r = 0; r < 8; r++) acc[r] = fmaf(zs[r][k], w, acc[r]);
    }
    const float bb = b1[col];
#pragma unroll
    for (int r = 0; r < 8; r++) g_a1[(rb + r) * 256 + col] = acc[r] + bb;
}

// ---------------- kstats1: layer-1 per-column double partials ---------------
__global__ __launch_bounds__(256) void kstats1() {
    const int tid = threadIdx.x, b = blockIdx.x;   // 64 blocks
    double s0 = 0.0, s1 = 0.0, q0 = 0.0, q1 = 0.0;
    const int rb = b * 128;
    for (int s = 0; s < 128; s += 2) {
        float v0 = g_a1[(rb + s) * 256 + tid];
        float v1 = g_a1[(rb + s + 1) * 256 + tid];
        s0 += (double)v0; q0 = fma((double)v0, (double)v0, q0);
        s1 += (double)v1; q1 = fma((double)v1, (double)v1, q1);
    }
    g_ps[b * 256 + tid] = s0 + s1;
    g_pq[b * 256 + tid] = q0 + q1;
}

// ---------------- kstats2a: layer-1 scale/shift (tiny) ----------------------
__global__ void kstats2a(const float* __restrict__ g1v,
                         const float* __restrict__ be1) {
    const int c = threadIdx.x;   // 256 threads
    double sa = 0.0, sb = 0.0, qa = 0.0, qb = 0.0;
    for (int b = 0; b < 64; b += 2) {
        sa += g_ps[b * 256 + c];       qa += g_pq[b * 256 + c];
        sb += g_ps[(b + 1) * 256 + c]; qb += g_pq[(b + 1) * 256 + c];
    }
    double s = sa + sb, q = qa + qb;
    double mean = s / (double)BN;
    double var  = q / (double)BN - mean * mean;
    float rstd = (float)(1.0 / sqrt(var + 1e-5));
    float scale = g1v[c] * rstd;
    g_sc1v[c] = scale;
    g_sh1v[c] = be1[c] - (float)mean * scale;
}

// ---------------- K3: a2 = relu(BN(a1)) @ W2 + b2, + L2 partials ------------
__global__ __launch_bounds__(256) void k3_gemm2(const float* __restrict__ W2,
                                                const float* __restrict__ b2) {
    __shared__ float h1s[16][256];
    __shared__ double sst[256], qst[256];
    const int rb = blockIdx.x * 16;
    const int tid = threadIdx.x;
    const float sc = g_sc1v[tid], sh = g_sh1v[tid];
#pragma unroll 4
    for (int r = 0; r < 16; r++) {
        float v = g_a1[(rb + r) * 256 + tid] * sc + sh;
        h1s[r][tid] = fmaxf(v, 0.0f);
    }
    __syncthreads();
    const int c  = tid & 63;
    const int rq = tid >> 6;
    float acc[4] = {0.f, 0.f, 0.f, 0.f};
    for (int k = 0; k < 256; k += 4) {
        float w0 = W2[(k + 0) * 64 + c];
        float w1 = W2[(k + 1) * 64 + c];
        float w2v = W2[(k + 2) * 64 + c];
        float w3v = W2[(k + 3) * 64 + c];
#pragma unroll
        for (int i = 0; i < 4; i++) {
            const float4 h = *reinterpret_cast<const float4*>(&h1s[rq * 4 + i][k]);
            acc[i] = fmaf(h.x, w0, acc[i]);
            acc[i] = fmaf(h.y, w1, acc[i]);
            acc[i] = fmaf(h.z, w2v, acc[i]);
            acc[i] = fmaf(h.w, w3v, acc[i]);
        }
    }
    const float bc = b2[c];
    float o[4];
#pragma unroll
    for (int i = 0; i < 4; i++) {
        o[i] = acc[i] + bc;
        g_a2[(rb + rq * 4 + i) * 64 + c] = o[i];
    }
    double s = (((double)o[0] + (double)o[1]) + (double)o[2]) + (double)o[3];
    double q = 0.0;
#pragma unroll
    for (int i = 0; i < 4; i++) q = fma((double)o[i], (double)o[i], q);
    sst[rq * 64 + c] = s; qst[rq * 64 + c] = q;
    __syncthreads();
    if (rq == 0) {
        double S = ((sst[c] + sst[64 + c]) + sst[128 + c]) + sst[192 + c];
        double Q = ((qst[c] + qst[64 + c]) + qst[128 + c]) + qst[192 + c];
        g_ps2[blockIdx.x * 64 + c] = S;
        g_pq2[blockIdx.x * 64 + c] = Q;
    }
}

// ---------------- kstats2b: layer-2 scale/shift (tiny) ----------------------
__global__ void kstats2b(const float* __restrict__ g2v,
                         const float* __restrict__ be2) {
    const int c = threadIdx.x;   // 64 threads
    double sa = 0.0, sb = 0.0, qa = 0.0, qb = 0.0;
    for (int b = 0; b < 512; b += 2) {
        sa += g_ps2[b * 64 + c];       qa += g_pq2[b * 64 + c];
        sb += g_ps2[(b + 1) * 64 + c]; qb += g_pq2[(b + 1) * 64 + c];
    }
    double S = sa + sb, Q = qa + qb;
    double mean = S / (double)BN;
    double var  = Q / (double)BN - mean * mean;
    float rstd = (float)(1.0 / sqrt(var + 1e-5));
    float scale = g2v[c] * rstd;
    g_sc2v[c] = scale;
    g_sh2v[c] = be2[c] - (float)mean * scale;
}

// ---------------- K5: two-pass bf16 MMA + exact-threshold candidate argmax --
// 256 blocks x 32 rows. Pass A: GEMM with register-only row max (no atomics,
// no smem traffic in the epilogue) -> exact global row max. Pass B: identical
// GEMM, append only logits >= max - MARGIN (true candidate set, ~6/row).
// Staging is 2xLDG.128 + 2xSTS.128 from pre-packed bf16x2 (k0pack).
__global__ __launch_bounds__(256) void k5_mma(const float* __restrict__ W3,
                                              const float* __restrict__ b3) {
    __shared__ float    h2f[32 * 68];
    __shared__ unsigned wsb[2 * 2304];      // 2 x [32 kp][72]
    __shared__ int      cand[32 * CAP];
    __shared__ unsigned rmx[32];
    __shared__ int      scnt[32];

    const int tid = threadIdx.x, lane = tid & 31, wid = tid >> 5;
    const int g = lane >> 2, c4 = lane & 3;
    const int rb = blockIdx.x * 32;

    for (int i = tid; i < 32 * 64; i += 256) {
        int r = i >> 6, k = i & 63;
        float v = g_a2[(rb + r) * 64 + k] * g_sc2v[k] + g_sh2v[k];
        h2f[r * 68 + k] = fmaxf(v, 0.0f);
    }
    if (tid < 32) { rmx[tid] = encf(-1e30f); scnt[tid] = 0; }
    __syncthreads();

    const int m  = wid & 1;    // m16 subtile
    const int nq = wid >> 1;   // n16 quarter of the 64-wide tile

    // A fragments (bf16, verified layout): [kstep][4]
    unsigned au[4][4];
#pragma unroll
    for (int s = 0; s < 4; s++) {
        int r0 = m * 16 + g, r1 = r0 + 8;
        int kA = 16 * s + 2 * c4, kB = kA + 8;
        au[s][0] = pkbf(h2f[r0 * 68 + kA], h2f[r0 * 68 + kA + 1]);
        au[s][1] = pkbf(h2f[r1 * 68 + kA], h2f[r1 * 68 + kA + 1]);
        au[s][2] = pkbf(h2f[r0 * 68 + kB], h2f[r0 * 68 + kB + 1]);
        au[s][3] = pkbf(h2f[r1 * 68 + kB], h2f[r1 * 68 + kB + 1]);
    }

    const int kp = tid >> 3, fq = tid & 7;
    const unsigned* wsrc = g_w3bf + kp * FN;

    const int rlo = m * 16 + g, rhi = rlo + 8;
    float rml = -1e30f, rmh = -1e30f;
    float thrlo = 0.f, thrhi = 0.f;

    for (int pass = 0; pass < 2; pass++) {
        // stage tile 0 into buffer 0
        {
            uint4 a = *reinterpret_cast<const uint4*>(wsrc + fq * 4);
            uint4 b = *reinterpret_cast<const uint4*>(wsrc + 32 + fq * 4);
            *reinterpret_cast<uint4*>(&wsb[kp * 72 + fq * 4]) = a;
            *reinterpret_cast<uint4*>(&wsb[kp * 72 + 32 + fq * 4]) = b;
        }
        __syncthreads();
        for (int t = 0; t < 128; t++) {
            unsigned* wcur = wsb + (t & 1) * 2304;
            uint4 pa, pb;
            if (t < 127) {
                pa = *reinterpret_cast<const uint4*>(wsrc + (t + 1) * 64 + fq * 4);
                pb = *reinterpret_cast<const uint4*>(wsrc + (t + 1) * 64 + 32 + fq * 4);
            }
            float acc[2][4];
#pragma unroll
            for (int h = 0; h < 2; h++) { acc[h][0] = acc[h][1] = acc[h][2] = acc[h][3] = 0.f; }
#pragma unroll
            for (int h = 0; h < 2; h++) {
                const int base = nq * 16 + h * 8 + g;
#pragma unroll
                for (int s = 0; s < 4; s++) {
                    unsigned bb0 = wcur[(8 * s + c4) * 72 + base];
                    unsigned bb1 = wcur[(8 * s + c4 + 4) * 72 + base];
                    mma_bf16(acc[h], au[s], bb0, bb1);
                }
            }
            const int f0 = t * 64;
            if (pass == 0) {
#pragma unroll
                for (int h = 0; h < 2; h++) {
                    const int fc = f0 + nq * 16 + h * 8 + 2 * c4;
                    const float2 bias = *reinterpret_cast<const float2*>(b3 + fc);
                    rml = fmaxf(rml, fmaxf(acc[h][0] + bias.x, acc[h][1] + bias.y));
                    rmh = fmaxf(rmh, fmaxf(acc[h][2] + bias.x, acc[h][3] + bias.y));
                }
            } else {
#pragma unroll
                for (int h = 0; h < 2; h++) {
                    const int fc = f0 + nq * 16 + h * 8 + 2 * c4;
                    const float2 bias = *reinterpret_cast<const float2*>(b3 + fc);
                    float v0 = acc[h][0] + bias.x, v1 = acc[h][1] + bias.y;
                    float v2 = acc[h][2] + bias.x, v3 = acc[h][3] + bias.y;
                    if (v0 > thrlo) { int p = atomicAdd(&scnt[rlo], 1); if (p < CAP) cand[rlo * CAP + p] = fc; }
                    if (v1 > thrlo) { int p = atomicAdd(&scnt[rlo], 1); if (p < CAP) cand[rlo * CAP + p] = fc + 1; }
                    if (v2 > thrhi) { int p = atomicAdd(&scnt[rhi], 1); if (p < CAP) cand[rhi * CAP + p] = fc; }
                    if (v3 > thrhi) { int p = atomicAdd(&scnt[rhi], 1); if (p < CAP) cand[rhi * CAP + p] = fc + 1; }
                }
            }
            if (t < 127) {
                unsigned* wnxt = wsb + ((t + 1) & 1) * 2304;
                *reinterpret_cast<uint4*>(&wnxt[kp * 72 + fq * 4]) = pa;
                *reinterpret_cast<uint4*>(&wnxt[kp * 72 + 32 + fq * 4]) = pb;
            }
            __syncthreads();
        }
        if (pass == 0) {
            atomicMax(&rmx[rlo], encf(rml));
            atomicMax(&rmx[rhi], encf(rmh));
            __syncthreads();
            thrlo = decf(rmx[rlo]) - MARGIN;
            thrhi = decf(rmx[rhi]) - MARGIN;
        }
    }
    __syncthreads();

    // ---- exact refine: warp w owns rows w, w+8, w+16, w+24 ----
    for (int rr = wid; rr < 32; rr += 8) {
        const int row = rb + rr;
        const int c = scnt[rr];
        float bestv = -1e30f; int bestf = 0x7FFFFFFF;
        if (c <= CAP) {
            for (int i = lane; i < c; i += 32) {
                int f = cand[rr * CAP + i];
                float dot = 0.f;
#pragma unroll
                for (int k = 0; k < 64; k++)
                    dot = fmaf(h2f[rr * 68 + k], W3[k * FN + f], dot);
                float logit = __fadd_rn(dot, b3[f]);
                float gg = gumbel_ref(jax_bits((unsigned)row * 8192u + (unsigned)f));
                float v = __fdiv_rn(__fadd_rn(logit, gg), 0.1f);
                if (v > bestv || (v == bestv && f < bestf)) { bestv = v; bestf = f; }
            }
        } else {   // overflow fallback (should never fire with exact threshold)
            float th = decf(rmx[rr]) - MARGIN;
            for (int f = lane; f < FN; f += 32) {
                float dot = 0.f;
#pragma unroll
                for (int k = 0; k < 64; k++)
                    dot = fmaf(h2f[rr * 68 + k], W3[k * FN + f], dot);
                float logit = __fadd_rn(dot, b3[f]);
                if (logit > th) {
                    float gg = gumbel_ref(jax_bits((unsigned)row * 8192u + (unsigned)f));
                    float v = __fdiv_rn(__fadd_rn(logit, gg), 0.1f);
                    if (v > bestv || (v == bestv && f < bestf)) { bestv = v; bestf = f; }
                }
            }
        }
#pragma unroll
        for (int off = 16; off > 0; off >>= 1) {
            float ov = __shfl_xor_sync(0xFFFFFFFFu, bestv, off);
            int   of = __shfl_xor_sync(0xFFFFFFFFu, bestf, off);
            if (ov > bestv || (ov == bestv && of < bestf)) { bestv = ov; bestf = of; }
        }
        if (lane == 0) g_ind[row] = bestf;
    }
}

// ---------------- K7: out[row] = codebook[ind[row]] -------------------------
__global__ void k7_gather(const float* __restrict__ codebook, float* __restrict__ out) {
    const int row = blockIdx.x;
    const int ind = g_ind[row];
    const float4* src = reinterpret_cast<const float4*>(codebook + (size_t)ind * DN);
    float4* dst = reinterpret_cast<float4*>(out + (size_t)row * DN);
    dst[threadIdx.x] = src[threadIdx.x];
}

// ---------------- launch ----------------------------------------------------
extern "C" void kernel_launch(void* const* d_in, const int* in_sizes, int n_in,
                              void* d_out, int out_size) {
    const float* x   = (const float*)d_in[0];
    const float* y   = (const float*)d_in[1];
    const float* W1  = (const float*)d_in[2];
    const float* b1  = (const float*)d_in[3];
    const float* g1  = (const float*)d_in[4];
    const float* be1 = (const float*)d_in[5];
    const float* W2  = (const float*)d_in[6];
    const float* b2  = (const float*)d_in[7];
    const float* g2  = (const float*)d_in[8];
    const float* be2 = (const float*)d_in[9];
    const float* W3  = (const float*)d_in[10];
    const float* b3  = (const float*)d_in[11];
    const float* cb  = (const float*)d_in[12];
    float* out = (float*)d_out;

    k0pack<<<1024, 256>>>(W3);
    k1_gemm1<<<BN / 8, 256>>>(x, y, W1, b1);
    kstats1<<<64, 256>>>();
    kstats2a<<<1, H1N>>>(g1, be1);
    k3_gemm2<<<BN / 16, 256>>>(W2, b2);
    kstats2b<<<1, H2N>>>(g2, be2);
    k5_mma<<<BN / 32, 256>>>(W3, b3);
    k7_gather<<<BN, 256>>>(cb, out);
}